// round 4
// baseline (speedup 1.0000x reference)
#include <cuda_runtime.h>
#include <cuda_bf16.h>
#include <cstdint>

// Banded stereo cost volume, 3 scales fused.
// cost[j,h,x] = sum_c L[c,h,x] * R[c,h,x-j], zero when x<j.
//
// Persistent-ish static schedule: grid = 152 CTAs (one per GB300 SM), each
// CTA walks a snake (boustrophedon) over 704 work units sorted heavy-first:
//   u [0,256):   scale0 row u, RIGHT half (x in [256,512), no zero band)
//   u [256,512): scale0 row u-256, LEFT half (x in [0,256))
//   u [512,640): scale1 full row
//   u [640,704): scale2 full row
// Snake over a descending-work list gives near-LPT balance (+-4%) vs the
// previous grid's ~25% wave-idle.
//
// Per unit: stage L segment (C*XW) and R window (C*(D+XW), left-zero-padded
// where needed) in SMEM; register-tile TJ=16 disparities x TX=4 columns per
// thread (16B lane stride -> all LDS.128 conflict-free).

#define THREADS 384
#define NCTAS   152
#define NUNITS  704

template <int C, int H, int W, int D, int XW>
__device__ __forceinline__ void cost_volume_chunk(const float* __restrict__ L,
                                                  const float* __restrict__ R,
                                                  float* __restrict__ out,
                                                  int h, int X0, float* smem)
{
    constexpr int RW = D + XW;          // R window width in smem
    float* sL = smem;                   // [C][XW]
    float* sR = smem + C * XW;          // [C][RW]

    const int tid = threadIdx.x;

    // Protect smem from the previous unit's readers.
    __syncthreads();

    // pad_len floats of zeros at the left of each sR channel row.
    const int pad_len   = (X0 >= D) ? 0 : (D - X0);   // 0 or D (X0 in {0, >=D})
    const int seg_start = X0 - D + pad_len;           // global x of first staged R elem
    const int seg_len   = RW - pad_len;

    for (int i = tid; i < C * pad_len; i += THREADS) {
        int c = i / pad_len;
        int k = i - c * pad_len;
        sR[c * RW + k] = 0.0f;
    }

    // Stage L [X0, X0+XW) and R [seg_start, seg_start+seg_len) per channel.
    // seg_start is a multiple of 4 -> float4 aligned.
    constexpr int WV = XW / 4;
    const float4* Lg = reinterpret_cast<const float4*>(L + (size_t)h * W + X0);
    const float4* Rg = reinterpret_cast<const float4*>(R + (size_t)h * W + seg_start);
    constexpr int CH_STRIDE_V = H * W / 4;
    const int SEGV = seg_len / 4;

    for (int i = tid; i < C * WV; i += THREADS) {
        int c  = i / WV;
        int xv = i - c * WV;
        reinterpret_cast<float4*>(sL + c * XW)[xv] = Lg[(size_t)c * CH_STRIDE_V + xv];
    }
    for (int i = tid; i < C * SEGV; i += THREADS) {
        int c  = i / SEGV;
        int xv = i - c * SEGV;
        reinterpret_cast<float4*>(sR + c * RW + pad_len)[xv] =
            Rg[(size_t)c * CH_STRIDE_V + xv];
    }
    __syncthreads();

    // Tile grid: TJ=16 disparities x TX=4 columns.
    constexpr int NXT = XW / 4;
    constexpr int NT  = (D / 16) * NXT;

    for (int t = tid; t < NT; t += THREADS) {
        int jt = t / NXT;               // NXT is pow2 -> shift
        int xt = t - jt * NXT;
        int j0 = jt * 16;
        int x0 = xt * 4;                // local x within chunk

        float* op = out + (size_t)j0 * H * W + (size_t)h * W + X0 + x0;

        // Tile fully inside the x<j zero band: write zeros, skip compute.
        if (X0 + x0 + 3 < j0) {
            float4 z = make_float4(0.f, 0.f, 0.f, 0.f);
#pragma unroll
            for (int jj = 0; jj < 16; jj++)
                *reinterpret_cast<float4*>(op + (size_t)jj * H * W) = z;
            continue;
        }

        float acc[16][4];
#pragma unroll
        for (int jj = 0; jj < 16; jj++)
#pragma unroll
            for (int xi = 0; xi < 4; xi++)
                acc[jj][xi] = 0.0f;

        // sR index of logical R[X0+x-j] is x + D - j (x local).
        // Window base x0 + D - j0 - 16 >= 0, multiple of 4 (16B aligned).
        const int rbase = x0 + D - j0 - 16;

#pragma unroll 4
        for (int c = 0; c < C; c++) {
            const float* sLc = sL + c * XW + x0;
            const float* sRc = sR + c * RW + rbase;

            float4 l4 = *reinterpret_cast<const float4*>(sLc);
            float lv[4] = {l4.x, l4.y, l4.z, l4.w};

            float rv[20];
#pragma unroll
            for (int q = 0; q < 5; q++) {
                float4 r4 = *reinterpret_cast<const float4*>(sRc + 4 * q);
                rv[4 * q + 0] = r4.x; rv[4 * q + 1] = r4.y;
                rv[4 * q + 2] = r4.z; rv[4 * q + 3] = r4.w;
            }

            // k = 16 + xi - jj in [1, 19]
#pragma unroll
            for (int jj = 0; jj < 16; jj++)
#pragma unroll
                for (int xi = 0; xi < 4; xi++)
                    acc[jj][xi] = fmaf(lv[xi], rv[16 + xi - jj], acc[jj][xi]);
        }

#pragma unroll
        for (int jj = 0; jj < 16; jj++) {
            float4 o = make_float4(acc[jj][0], acc[jj][1], acc[jj][2], acc[jj][3]);
            *reinterpret_cast<float4*>(op + (size_t)jj * H * W) = o;
        }
    }
}

// Output layout: cv0 (1,192,256,512) | cv1 (1,96,128,256) | cv2 (1,48,64,128)
static constexpr size_t OUT0_ELEMS = (size_t)192 * 256 * 512;
static constexpr size_t OUT1_ELEMS = (size_t)96 * 128 * 256;

__global__ void __launch_bounds__(THREADS, 1)
cost_volume_fused_kernel(const float* __restrict__ L0, const float* __restrict__ R0,
                         const float* __restrict__ L1, const float* __restrict__ R1,
                         const float* __restrict__ L2, const float* __restrict__ R2,
                         float* __restrict__ out)
{
    extern __shared__ float smem[];
    const int k = blockIdx.x;

#pragma unroll 1
    for (int r = 0; r < 5; r++) {
        int u = r * NCTAS + ((r & 1) ? (NCTAS - 1 - k) : k);
        if (u >= NUNITS) continue;

        if (u < 512) {
            // scale 0, half-row
            int h  = (u < 256) ? u : (u - 256);
            int X0 = (u < 256) ? 256 : 0;     // right halves first (heaviest)
            cost_volume_chunk<32, 256, 512, 192, 256>(L0, R0, out, h, X0, smem);
        } else if (u < 640) {
            cost_volume_chunk<32, 128, 256, 96, 256>(L1, R1, out + OUT0_ELEMS,
                                                     u - 512, 0, smem);
        } else {
            cost_volume_chunk<32, 64, 128, 48, 128>(L2, R2,
                                                    out + OUT0_ELEMS + OUT1_ELEMS,
                                                    u - 640, 0, smem);
        }
    }
}

extern "C" void kernel_launch(void* const* d_in, const int* in_sizes, int n_in,
                              void* d_out, int out_size)
{
    const float* L0 = (const float*)d_in[0];
    const float* R0 = (const float*)d_in[1];
    const float* L1 = (const float*)d_in[2];
    const float* R1 = (const float*)d_in[3];
    const float* L2 = (const float*)d_in[4];
    const float* R2 = (const float*)d_in[5];
    float* out = (float*)d_out;

    // Max smem: scale0 chunk = 32*(256 + 192+256)*4 = 90112 bytes
    constexpr int SMEM_BYTES = 32 * (256 + 192 + 256) * 4;
    static bool attr_set = false;
    if (!attr_set) {
        cudaFuncSetAttribute(cost_volume_fused_kernel,
                             cudaFuncAttributeMaxDynamicSharedMemorySize, SMEM_BYTES);
        attr_set = true;
    }

    cost_volume_fused_kernel<<<NCTAS, THREADS, SMEM_BYTES>>>(L0, R0, L1, R1,
                                                             L2, R2, out);
}

// round 7
// speedup vs baseline: 1.2341x; 1.2341x over previous
#include <cuda_runtime.h>
#include <cuda_bf16.h>
#include <cstdint>

// Banded stereo cost volume, 3 scales fused.
// cost[j,h,x] = sum_c L[c,h,x] * R[c,h,x-j], zero when x<j.
//
// Round-2 structure (one CTA per image row, 448 CTAs, 512 threads, SMEM-staged
// rows, TJ=16 x TX=4 register tile) with the inner product rewritten around
// packed fma.rn.f32x2 (SASS FFMA2):
//   R loaded as ulonglong2 -> even float-pairs pre-packed for free
//   even jj: 2 FFMA2   (xi pairs (0,1),(2,3), R offsets even)
//   odd  jj: 1 FFMA2 on xi=(1,2) (R offset 17-jj even) + 2 scalar FFMA
// => 40 FMA-pipe instr per channel (was 64); crossbar (6 LDS.128) now binds.

#define THREADS 512

using u64 = unsigned long long;

__device__ __forceinline__ u64 pack2(float lo, float hi) {
    u64 r; asm("mov.b64 %0, {%1, %2};" : "=l"(r) : "f"(lo), "f"(hi)); return r;
}
__device__ __forceinline__ void unpack2(u64 p, float& lo, float& hi) {
    asm("mov.b64 {%0, %1}, %2;" : "=f"(lo), "=f"(hi) : "l"(p));
}
__device__ __forceinline__ u64 fma2(u64 a, u64 b, u64 c) {
    u64 d; asm("fma.rn.f32x2 %0, %1, %2, %3;" : "=l"(d) : "l"(a), "l"(b), "l"(c));
    return d;
}

template <int C, int H, int W, int D>
__device__ __forceinline__ void cost_volume_row(const float* __restrict__ L,
                                                const float* __restrict__ R,
                                                float* __restrict__ out,
                                                int h, float* smem)
{
    constexpr int RW = D + W;           // padded R row width
    float* sL = smem;                   // [C][W]
    float* sR = smem + C * W;           // [C][RW], first D floats/channel = 0

    const int tid = threadIdx.x;

    // Zero the pad region (C*D elements)
    for (int i = tid; i < C * D; i += THREADS) {
        int c = i / D;
        int k = i - c * D;
        sR[c * RW + k] = 0.0f;
    }

    // Stage L and R rows (float4 vectorized). Channel stride in gmem = H*W.
    constexpr int WV = W / 4;
    const float4* Lg = reinterpret_cast<const float4*>(L + (size_t)h * W);
    const float4* Rg = reinterpret_cast<const float4*>(R + (size_t)h * W);
    constexpr int CH_STRIDE_V = H * W / 4;
    for (int i = tid; i < C * WV; i += THREADS) {
        int c  = i / WV;
        int xv = i - c * WV;
        float4 lv = Lg[(size_t)c * CH_STRIDE_V + xv];
        float4 rv = Rg[(size_t)c * CH_STRIDE_V + xv];
        reinterpret_cast<float4*>(sL + c * W)[xv] = lv;
        reinterpret_cast<float4*>(sR + c * RW + D)[xv] = rv;
    }
    __syncthreads();

    // Tile grid: TJ=16 disparities x TX=4 columns per tile.
    constexpr int NXT = W / 4;              // x tiles (pow2)
    constexpr int NT  = (D / 16) * NXT;

    for (int t = tid; t < NT; t += THREADS) {
        int jt = t / NXT;                   // shift (NXT pow2)
        int xt = t - jt * NXT;
        int j0 = jt * 16;
        int x0 = xt * 4;

        float* op = out + (size_t)j0 * H * W + (size_t)h * W + x0;

        // Tile fully inside the x<j zero band: write zeros, skip compute.
        if (x0 + 3 < j0) {
            float4 z = make_float4(0.f, 0.f, 0.f, 0.f);
#pragma unroll
            for (int jj = 0; jj < 16; jj++)
                *reinterpret_cast<float4*>(op + (size_t)jj * H * W) = z;
            continue;
        }

        // Accumulators:
        //  even jj=2t:  accE[t][0] = (acc[x0],acc[x0+1]), accE[t][1] = (x0+2,x0+3)
        //  odd  jj=2t+1: accO[t] = (acc[x0+1],acc[x0+2]); accS[t][0]=x0, [1]=x0+3
        u64 accE[8][2], accO[8];
        float accS[8][2];
#pragma unroll
        for (int tt = 0; tt < 8; tt++) {
            accE[tt][0] = 0ULL; accE[tt][1] = 0ULL; accO[tt] = 0ULL;
            accS[tt][0] = 0.0f; accS[tt][1] = 0.0f;
        }

        // sR index of logical R[x-j] is D + x - j.
        // Window base D + x0 - j0 - 16: >= 0, multiple of 4 (16B aligned).
        const int rbase = D + x0 - j0 - 16;

#pragma unroll 4
        for (int c = 0; c < C; c++) {
            const float* sLc = sL + c * W + x0;
            const float* sRc = sR + c * RW + rbase;

            // L: one LDS.128 -> two packed pairs + scalar aliases + mid pair
            ulonglong2 lt = *reinterpret_cast<const ulonglong2*>(sLc);
            u64 lp0 = lt.x, lp1 = lt.y;
            float l0, l1, l2, l3;
            unpack2(lp0, l0, l1);
            unpack2(lp1, l2, l3);
            u64 lmid = pack2(l1, l2);

            // R: five LDS.128 -> re[k] = (rv[2k], rv[2k+1]), k = 0..9
            u64 re[10];
#pragma unroll
            for (int q = 0; q < 5; q++) {
                ulonglong2 rq = reinterpret_cast<const ulonglong2*>(sRc)[q];
                re[2 * q]     = rq.x;
                re[2 * q + 1] = rq.y;
            }

            // rv[16+xi-jj]: even jj=2t uses re[8-t], re[9-t];
            // odd jj=2t+1 uses re[8-t] (xi=1,2), hi(re[7-t]) (xi=0), lo(re[9-t]) (xi=3)
#pragma unroll
            for (int tt = 0; tt < 8; tt++) {
                accE[tt][0] = fma2(lp0, re[8 - tt], accE[tt][0]);
                accE[tt][1] = fma2(lp1, re[9 - tt], accE[tt][1]);
                accO[tt]    = fma2(lmid, re[8 - tt], accO[tt]);
                float rl7, rh7, rl9, rh9;
                unpack2(re[7 - tt], rl7, rh7);   // need hi
                unpack2(re[9 - tt], rl9, rh9);   // need lo
                accS[tt][0] = fmaf(l0, rh7, accS[tt][0]);
                accS[tt][1] = fmaf(l3, rl9, accS[tt][1]);
            }
        }

#pragma unroll
        for (int tt = 0; tt < 8; tt++) {
            float a0, a1, a2, a3;
            unpack2(accE[tt][0], a0, a1);
            unpack2(accE[tt][1], a2, a3);
            *reinterpret_cast<float4*>(op + (size_t)(2 * tt) * H * W) =
                make_float4(a0, a1, a2, a3);
            float b1, b2;
            unpack2(accO[tt], b1, b2);
            *reinterpret_cast<float4*>(op + (size_t)(2 * tt + 1) * H * W) =
                make_float4(accS[tt][0], b1, b2, accS[tt][1]);
        }
    }
}

// Output layout: cv0 (1,192,256,512) | cv1 (1,96,128,256) | cv2 (1,48,64,128)
static constexpr size_t OUT0_ELEMS = (size_t)192 * 256 * 512;
static constexpr size_t OUT1_ELEMS = (size_t)96 * 128 * 256;

__global__ void __launch_bounds__(THREADS, 1)
cost_volume_fused_kernel(const float* __restrict__ L0, const float* __restrict__ R0,
                         const float* __restrict__ L1, const float* __restrict__ R1,
                         const float* __restrict__ L2, const float* __restrict__ R2,
                         float* __restrict__ out)
{
    extern __shared__ float smem[];
    int b = blockIdx.x;
    if (b < 256) {
        cost_volume_row<32, 256, 512, 192>(L0, R0, out, b, smem);
    } else if (b < 256 + 128) {
        cost_volume_row<32, 128, 256, 96>(L1, R1, out + OUT0_ELEMS, b - 256, smem);
    } else {
        cost_volume_row<32, 64, 128, 48>(L2, R2, out + OUT0_ELEMS + OUT1_ELEMS,
                                         b - 256 - 128, smem);
    }
}

extern "C" void kernel_launch(void* const* d_in, const int* in_sizes, int n_in,
                              void* d_out, int out_size)
{
    const float* L0 = (const float*)d_in[0];
    const float* R0 = (const float*)d_in[1];
    const float* L1 = (const float*)d_in[2];
    const float* R1 = (const float*)d_in[3];
    const float* L2 = (const float*)d_in[4];
    const float* R2 = (const float*)d_in[5];
    float* out = (float*)d_out;

    // Worst-case smem: scale 0 -> 32*(512 + 192+512)*4 = 155648 bytes
    constexpr int SMEM_BYTES = 32 * (512 + 192 + 512) * 4;
    static bool attr_set = false;
    if (!attr_set) {
        cudaFuncSetAttribute(cost_volume_fused_kernel,
                             cudaFuncAttributeMaxDynamicSharedMemorySize, SMEM_BYTES);
        attr_set = true;
    }

    // 256 + 128 + 64 = 448 blocks; heavy scale-0 rows first.
    cost_volume_fused_kernel<<<448, THREADS, SMEM_BYTES>>>(L0, R0, L1, R1, L2, R2, out);
}

// round 10
// speedup vs baseline: 1.2392x; 1.0041x over previous
#include <cuda_runtime.h>
#include <cuda_bf16.h>
#include <cstdint>

// Banded stereo cost volume, 3 scales fused.
// cost[j,h,x] = sum_c L[c,h,x] * R[c,h,x-j], zero when x<j.
//
// Round-2 structure (one CTA per image row, 448 CTAs, 512 threads, SMEM-staged
// rows, TJ=16 x TX=4 register tile) + packed fma.rn.f32x2 core, restructured
// so NO pack/unpack movs sit in the hot tt-loop:
//   - R and L loaded as float4 (scalar regs, free scalar access for odd-jj FFMAs)
//   - packed u64 views built once per channel from ALIGNED reg pairs
//     (coalescible by ptxas); only lmid=(l1,l2) materializes
//   - accumulators stay packed across the channel loop; unpacked once per tile
// Per channel: 6 LDS.128 + 24 FFMA2 + 16 FFMA (was 64 FFMA in round 2).

#define THREADS 512

using u64 = unsigned long long;

__device__ __forceinline__ u64 pack2(float lo, float hi) {
    u64 r; asm("mov.b64 %0, {%1, %2};" : "=l"(r) : "f"(lo), "f"(hi)); return r;
}
__device__ __forceinline__ void unpack2(u64 p, float& lo, float& hi) {
    asm("mov.b64 {%0, %1}, %2;" : "=f"(lo), "=f"(hi) : "l"(p));
}
__device__ __forceinline__ u64 fma2(u64 a, u64 b, u64 c) {
    u64 d; asm("fma.rn.f32x2 %0, %1, %2, %3;" : "=l"(d) : "l"(a), "l"(b), "l"(c));
    return d;
}

template <int C, int H, int W, int D>
__device__ __forceinline__ void cost_volume_row(const float* __restrict__ L,
                                                const float* __restrict__ R,
                                                float* __restrict__ out,
                                                int h, float* smem)
{
    constexpr int RW = D + W;           // padded R row width
    float* sL = smem;                   // [C][W]
    float* sR = smem + C * W;           // [C][RW], first D floats/channel = 0

    const int tid = threadIdx.x;

    // Zero the pad region (C*D elements)
    for (int i = tid; i < C * D; i += THREADS) {
        int c = i / D;
        int k = i - c * D;
        sR[c * RW + k] = 0.0f;
    }

    // Stage L and R rows (float4 vectorized). Channel stride in gmem = H*W.
    constexpr int WV = W / 4;
    const float4* Lg = reinterpret_cast<const float4*>(L + (size_t)h * W);
    const float4* Rg = reinterpret_cast<const float4*>(R + (size_t)h * W);
    constexpr int CH_STRIDE_V = H * W / 4;
    for (int i = tid; i < C * WV; i += THREADS) {
        int c  = i / WV;
        int xv = i - c * WV;
        float4 lv = Lg[(size_t)c * CH_STRIDE_V + xv];
        float4 rv = Rg[(size_t)c * CH_STRIDE_V + xv];
        reinterpret_cast<float4*>(sL + c * W)[xv] = lv;
        reinterpret_cast<float4*>(sR + c * RW + D)[xv] = rv;
    }
    __syncthreads();

    // Tile grid: TJ=16 disparities x TX=4 columns per tile.
    constexpr int NXT = W / 4;              // x tiles (pow2)
    constexpr int NT  = (D / 16) * NXT;

    for (int t = tid; t < NT; t += THREADS) {
        int jt = t / NXT;                   // shift (NXT pow2)
        int xt = t - jt * NXT;
        int j0 = jt * 16;
        int x0 = xt * 4;

        float* op = out + (size_t)j0 * H * W + (size_t)h * W + x0;

        // Tile fully inside the x<j zero band: write zeros, skip compute.
        if (x0 + 3 < j0) {
            float4 z = make_float4(0.f, 0.f, 0.f, 0.f);
#pragma unroll
            for (int jj = 0; jj < 16; jj++)
                *reinterpret_cast<float4*>(op + (size_t)jj * H * W) = z;
            continue;
        }

        // Accumulators:
        //  even jj=2t:  accE[t][0]=(acc[x0],acc[x0+1]), accE[t][1]=(x0+2,x0+3)
        //  odd  jj=2t+1: accO[t]=(acc[x0+1],acc[x0+2]); accS[t][0]=x0, [1]=x0+3
        u64 accE[8][2], accO[8];
        float accS[8][2];
#pragma unroll
        for (int tt = 0; tt < 8; tt++) {
            accE[tt][0] = 0ULL; accE[tt][1] = 0ULL; accO[tt] = 0ULL;
            accS[tt][0] = 0.0f; accS[tt][1] = 0.0f;
        }

        // sR index of logical R[x-j] is D + x - j.
        // Window base D + x0 - j0 - 16: >= 0, multiple of 4 (16B aligned).
        const int rbase = D + x0 - j0 - 16;

#pragma unroll 4
        for (int c = 0; c < C; c++) {
            const float* sLc = sL + c * W + x0;
            const float* sRc = sR + c * RW + rbase;

            // L: float4 load -> scalars native; packed views from aligned pairs
            float4 l4 = *reinterpret_cast<const float4*>(sLc);
            u64 lp0  = pack2(l4.x, l4.y);   // aligned pair -> coalescible
            u64 lp1  = pack2(l4.z, l4.w);   // aligned pair -> coalescible
            u64 lmid = pack2(l4.y, l4.z);   // misaligned -> materializes (ok)

            // R: five float4 loads -> scalars rv[0..19] + even packs re[0..9]
            float4 r4[5];
#pragma unroll
            for (int q = 0; q < 5; q++)
                r4[q] = *reinterpret_cast<const float4*>(sRc + 4 * q);

            float rv[20];
            u64 re[10];
#pragma unroll
            for (int q = 0; q < 5; q++) {
                rv[4 * q + 0] = r4[q].x; rv[4 * q + 1] = r4[q].y;
                rv[4 * q + 2] = r4[q].z; rv[4 * q + 3] = r4[q].w;
                re[2 * q]     = pack2(r4[q].x, r4[q].y);  // aligned pair
                re[2 * q + 1] = pack2(r4[q].z, r4[q].w);  // aligned pair
            }

            // even jj=2tt: rv[16+xi-2tt] -> pairs re[8-tt] (xi 0,1), re[9-tt] (xi 2,3)
            // odd  jj=2tt+1: xi=1,2 -> pair re[8-tt]; xi=0 -> rv[15-2tt]; xi=3 -> rv[18-2tt]
#pragma unroll
            for (int tt = 0; tt < 8; tt++) {
                accE[tt][0] = fma2(lp0,  re[8 - tt], accE[tt][0]);
                accE[tt][1] = fma2(lp1,  re[9 - tt], accE[tt][1]);
                accO[tt]    = fma2(lmid, re[8 - tt], accO[tt]);
                accS[tt][0] = fmaf(l4.x, rv[15 - 2 * tt], accS[tt][0]);
                accS[tt][1] = fmaf(l4.w, rv[18 - 2 * tt], accS[tt][1]);
            }
        }

#pragma unroll
        for (int tt = 0; tt < 8; tt++) {
            float a0, a1, a2, a3;
            unpack2(accE[tt][0], a0, a1);
            unpack2(accE[tt][1], a2, a3);
            *reinterpret_cast<float4*>(op + (size_t)(2 * tt) * H * W) =
                make_float4(a0, a1, a2, a3);
            float b1, b2;
            unpack2(accO[tt], b1, b2);
            *reinterpret_cast<float4*>(op + (size_t)(2 * tt + 1) * H * W) =
                make_float4(accS[tt][0], b1, b2, accS[tt][1]);
        }
    }
}

// Output layout: cv0 (1,192,256,512) | cv1 (1,96,128,256) | cv2 (1,48,64,128)
static constexpr size_t OUT0_ELEMS = (size_t)192 * 256 * 512;
static constexpr size_t OUT1_ELEMS = (size_t)96 * 128 * 256;

__global__ void __launch_bounds__(THREADS, 1)
cost_volume_fused_kernel(const float* __restrict__ L0, const float* __restrict__ R0,
                         const float* __restrict__ L1, const float* __restrict__ R1,
                         const float* __restrict__ L2, const float* __restrict__ R2,
                         float* __restrict__ out)
{
    extern __shared__ float smem[];
    int b = blockIdx.x;
    if (b < 256) {
        cost_volume_row<32, 256, 512, 192>(L0, R0, out, b, smem);
    } else if (b < 256 + 128) {
        cost_volume_row<32, 128, 256, 96>(L1, R1, out + OUT0_ELEMS, b - 256, smem);
    } else {
        cost_volume_row<32, 64, 128, 48>(L2, R2, out + OUT0_ELEMS + OUT1_ELEMS,
                                         b - 256 - 128, smem);
    }
}

extern "C" void kernel_launch(void* const* d_in, const int* in_sizes, int n_in,
                              void* d_out, int out_size)
{
    const float* L0 = (const float*)d_in[0];
    const float* R0 = (const float*)d_in[1];
    const float* L1 = (const float*)d_in[2];
    const float* R1 = (const float*)d_in[3];
    const float* L2 = (const float*)d_in[4];
    const float* R2 = (const float*)d_in[5];
    float* out = (float*)d_out;

    // Worst-case smem: scale 0 -> 32*(512 + 192+512)*4 = 155648 bytes
    constexpr int SMEM_BYTES = 32 * (512 + 192 + 512) * 4;
    static bool attr_set = false;
    if (!attr_set) {
        cudaFuncSetAttribute(cost_volume_fused_kernel,
                             cudaFuncAttributeMaxDynamicSharedMemorySize, SMEM_BYTES);
        attr_set = true;
    }

    // 256 + 128 + 64 = 448 blocks; heavy scale-0 rows first.
    cost_volume_fused_kernel<<<448, THREADS, SMEM_BYTES>>>(L0, R0, L1, R1, L2, R2, out);
}